// round 10
// baseline (speedup 1.0000x reference)
#include <cuda_runtime.h>
#include <cstdint>
#include <math.h>

// ---------------- problem dims ----------------
#define BB 8
#define LL 4096
#define DD 1024
#define MTOT (BB * LL)            // 32768
#define NVIRT (2 * DD)            // 2048 virtual N (Wg | Wh)

// GEMM tiling
#define BM 128
#define BN 128
#define BK 32
#define NCH (DD / BK)             // 32 k-chunks
#define NS 3                      // pipeline stages

#define STAGE_A_BYTES (BM * BK * 4)   // 16 KB
#define STAGE_B_BYTES (BN * BK * 4)   // 16 KB
#define STAGE_BYTES (STAGE_A_BYTES + STAGE_B_BYTES)
#define SMEM_NEEDED (NS * STAGE_BYTES)   // 96 KB -> 2 CTA/SM

// scan chunking
#define NCHUNK 16
#define TCHUNK (LL / NCHUNK)      // 256
#define NCHAN (BB * DD)           // 8192

// ---------------- device scratch ----------------
// NOTE: g must be fp32 — the recurrence amplifies gate error by 1/(1-g);
// fp16 storage failed with rel_err 4.4e-2 (R9).
__device__ float g_G[(size_t)MTOT * DD];     // sigmoid gate
__device__ float g_C[(size_t)MTOT * DD];     // tanh candidate
__device__ float g_Xr[(size_t)MTOT * DD];    // x pre-rounded to tf32 (RNA)
__device__ float g_Wr[(size_t)NVIRT * DD];   // [Wg ; Wh] pre-rounded to tf32
__device__ float g_AggA[NCHUNK * NCHAN];
__device__ float g_AggB[NCHUNK * NCHAN];
__device__ float g_Carry[NCHUNK * NCHAN];

// ---------------- helpers ----------------
__device__ __forceinline__ uint32_t smem_to_u32(const void* p) {
    uint32_t a;
    asm("{ .reg .u64 t; cvta.to.shared.u64 t, %1; cvt.u32.u64 %0, t; }" : "=r"(a) : "l"(p));
    return a;
}
__device__ __forceinline__ void cp_async16(uint32_t saddr, const void* gaddr) {
    asm volatile("cp.async.cg.shared.global [%0], [%1], 16;" :: "r"(saddr), "l"(gaddr));
}
__device__ __forceinline__ void cp_commit() { asm volatile("cp.async.commit_group;" ::: "memory"); }
__device__ __forceinline__ void cp_wait1() { asm volatile("cp.async.wait_group 1;" ::: "memory"); }

__device__ __forceinline__ void ldsm_x4(uint32_t& r0, uint32_t& r1, uint32_t& r2, uint32_t& r3,
                                        uint32_t addr) {
    asm volatile("ldmatrix.sync.aligned.m8n8.x4.shared.b16 {%0,%1,%2,%3}, [%4];"
                 : "=r"(r0), "=r"(r1), "=r"(r2), "=r"(r3) : "r"(addr));
}
__device__ __forceinline__ void mma_tf32(float* c, const uint32_t* a, const uint32_t* b) {
    asm volatile(
        "mma.sync.aligned.m16n8k8.row.col.f32.tf32.tf32.f32 "
        "{%0,%1,%2,%3}, {%4,%5,%6,%7}, {%8,%9}, {%0,%1,%2,%3};"
        : "+f"(c[0]), "+f"(c[1]), "+f"(c[2]), "+f"(c[3])
        : "r"(a[0]), "r"(a[1]), "r"(a[2]), "r"(a[3]), "r"(b[0]), "r"(b[1]));
}

// swizzled smem offset for (row, 16B-chunk) with 128B rows
__device__ __forceinline__ uint32_t sw_off(int row, int chunk) {
    return (uint32_t)(row * 128 + ((chunk ^ (row & 7)) << 4));
}

// ---------------------------------------------------------------------------
// tf32 pre-round (RNA) pass.
// ---------------------------------------------------------------------------
__global__ __launch_bounds__(256)
void round_tf32_kernel(const float* __restrict__ in, float* __restrict__ out, int n4)
{
    int i = blockIdx.x * 256 + threadIdx.x;
    if (i >= n4) return;
    float4 v = ((const float4*)in)[i];
    uint32_t a, b, c, d;
    asm("cvt.rna.tf32.f32 %0, %1;" : "=r"(a) : "f"(v.x));
    asm("cvt.rna.tf32.f32 %0, %1;" : "=r"(b) : "f"(v.y));
    asm("cvt.rna.tf32.f32 %0, %1;" : "=r"(c) : "f"(v.z));
    asm("cvt.rna.tf32.f32 %0, %1;" : "=r"(d) : "f"(v.w));
    float4 o;
    o.x = __uint_as_float(a); o.y = __uint_as_float(b);
    o.z = __uint_as_float(c); o.w = __uint_as_float(d);
    ((float4*)out)[i] = o;
}

// ---------------------------------------------------------------------------
// tf32 mma.sync GEMM + bias + activation epilogue.
// grid = (NVIRT/BN = 16, MTOT/BM = 256), 256 threads (wm2 x wn4),
// warp tile 64x32. Single __syncthreads per k-chunk (multistage order).
// ---------------------------------------------------------------------------
__global__ __launch_bounds__(256, 2)
void gemm_mma_kernel(const float* __restrict__ bg, const float* __restrict__ bh)
{
    extern __shared__ char smem_raw[];
    const uint32_t s0 = smem_to_u32(smem_raw);

    const int tid = threadIdx.x;
    const int wid = tid >> 5;
    const int lane = tid & 31;
    const int wm = wid >> 2;          // 0..1  -> 64-row band
    const int wn = wid & 3;           // 0..3  -> 32-col band

    const int m0 = blockIdx.y * BM;
    const int n0 = blockIdx.x * BN;   // virtual col
    const bool second = (n0 >= DD);
    const int n0r = n0 & (DD - 1);
    const float* __restrict__ bias = second ? bh : bg;
    float* __restrict__ outp = second ? g_C : g_G;

    const float* xa0 = g_Xr + (size_t)m0 * DD;
    const float* wb0 = g_Wr + (size_t)n0 * DD;   // virtual row in [Wg;Wh]

    auto load_stage = [&](int s, int kc) {
        const uint32_t sa = s0 + (uint32_t)s * STAGE_BYTES;
        const uint32_t sb = sa + STAGE_A_BYTES;
        const int kt = kc * BK;
#pragma unroll
        for (int i = 0; i < 4; i++) {
            int u = i * 256 + tid;
            int r = u >> 3, c = u & 7;
            cp_async16(sa + sw_off(r, c), xa0 + (size_t)r * DD + kt + c * 4);
        }
#pragma unroll
        for (int i = 0; i < 4; i++) {
            int u = i * 256 + tid;
            int r = u >> 3, c = u & 7;
            cp_async16(sb + sw_off(r, c), wb0 + (size_t)r * DD + kt + c * 4);
        }
    };

    float acc[4][4][4];               // [m-tile][n-tile][frag]
#pragma unroll
    for (int i = 0; i < 4; i++)
#pragma unroll
        for (int j = 0; j < 4; j++)
#pragma unroll
            for (int q = 0; q < 4; q++) acc[i][j][q] = 0.f;

    // prologue: stages 0..NS-2
    load_stage(0, 0); cp_commit();
    load_stage(1, 1); cp_commit();

    const int q = lane >> 3, rr = lane & 7;

    for (int k = 0; k < NCH; k++) {
        cp_wait1();                    // stage k data arrived (this thread)
        __syncthreads();               // all threads; also orders prior-stage reads
        const int kl = k + NS - 1;
        if (kl < NCH) load_stage(kl % NS, kl);   // overwrites stage read in iter k-1: safe post-sync
        cp_commit();                   // one group per iteration (possibly empty)

        const uint32_t sa = s0 + (uint32_t)(k % NS) * STAGE_BYTES;
        const uint32_t sb = sa + STAGE_A_BYTES;

#pragma unroll
        for (int kk8 = 0; kk8 < 4; kk8++) {      // four k8 steps in BK=32
            const int ch = kk8 * 2;              // 16B-chunk base (k8 = 2 chunks)
            uint32_t afr[4][4];
#pragma unroll
            for (int mt = 0; mt < 4; mt++) {
                int row = wm * 64 + mt * 16 + ((q & 1) << 3) + rr;
                int chunk = ch + (q >> 1);
                ldsm_x4(afr[mt][0], afr[mt][1], afr[mt][2], afr[mt][3],
                        sa + sw_off(row, chunk));
            }
            uint32_t bfr[4][2];
#pragma unroll
            for (int p = 0; p < 2; p++) {        // each x4 covers two n8-tiles
                int row = wn * 32 + p * 16 + ((q >> 1) << 3) + rr;
                int chunk = ch + (q & 1);
                uint32_t r0, r1, r2, r3;
                ldsm_x4(r0, r1, r2, r3, sb + sw_off(row, chunk));
                bfr[p * 2 + 0][0] = r0; bfr[p * 2 + 0][1] = r1;
                bfr[p * 2 + 1][0] = r2; bfr[p * 2 + 1][1] = r3;
            }
#pragma unroll
            for (int mt = 0; mt < 4; mt++)
#pragma unroll
                for (int nt = 0; nt < 4; nt++)
                    mma_tf32(acc[mt][nt], afr[mt], bfr[nt]);
        }
    }

    // ---- epilogue: bias + activation, float2 stores ----
    const int crow = lane >> 2;            // 0..7
    const int ccol = (lane & 3) * 2;       // 0,2,4,6
#pragma unroll
    for (int nt = 0; nt < 4; nt++) {
        const int col = wn * 32 + nt * 8 + ccol;
        const float2 bv = *(const float2*)&bias[n0r + col];
#pragma unroll
        for (int mt = 0; mt < 4; mt++) {
#pragma unroll
            for (int h = 0; h < 2; h++) {  // c0/c1 then c2/c3 (row, row+8)
                const int m = m0 + wm * 64 + mt * 16 + crow + h * 8;
                float t0 = acc[mt][nt][h * 2 + 0] + bv.x;
                float t1 = acc[mt][nt][h * 2 + 1] + bv.y;
                float2 o;
                if (second) { o.x = tanhf(t0); o.y = tanhf(t1); }
                else {
                    o.x = 1.0f / (1.0f + __expf(-t0));
                    o.y = 1.0f / (1.0f + __expf(-t1));
                }
                *(float2*)&outp[(size_t)m * DD + n0r + col] = o;
            }
        }
    }
}

// ---------------------------------------------------------------------------
// Scan phase A: per (channel, chunk) affine aggregate over TCHUNK steps.
// ---------------------------------------------------------------------------
__global__ __launch_bounds__(256)
void scan_aggregate_kernel()
{
    const int bx = blockIdx.x;
    const int dgrp = bx & 3;
    const int chunk = (bx >> 2) & (NCHUNK - 1);
    const int b = bx >> 6;
    const int d = dgrp * 256 + threadIdx.x;

    size_t base = ((size_t)(b * LL + chunk * TCHUNK)) * DD + d;
    float A = 1.0f, Bc = 0.0f;
#pragma unroll 8
    for (int t = 0; t < TCHUNK; t++) {
        float g = g_G[base];
        float c = g_C[base];
        float bt = (1.0f - g) * c;
        Bc = fmaf(g, Bc, bt);
        A *= g;
        base += DD;
    }
    const int ch = b * DD + d;
    g_AggA[chunk * NCHAN + ch] = A;
    g_AggB[chunk * NCHAN + ch] = Bc;
}

// ---------------------------------------------------------------------------
// Scan phase B: sequential scan of chunk aggregates per channel.
// ---------------------------------------------------------------------------
__global__ __launch_bounds__(256)
void scan_carry_kernel(const float* __restrict__ hidden)
{
    const int ch = blockIdx.x * 256 + threadIdx.x;
    float h = hidden[ch];
#pragma unroll
    for (int k = 0; k < NCHUNK; k++) {
        g_Carry[k * NCHAN + ch] = h;
        h = fmaf(g_AggA[k * NCHAN + ch], h, g_AggB[k * NCHAN + ch]);
    }
}

// ---------------------------------------------------------------------------
// Scan phase C: apply within-chunk recurrence from carry, write output.
// ---------------------------------------------------------------------------
__global__ __launch_bounds__(256)
void scan_apply_kernel(float* __restrict__ out)
{
    const int bx = blockIdx.x;
    const int dgrp = bx & 3;
    const int chunk = (bx >> 2) & (NCHUNK - 1);
    const int b = bx >> 6;
    const int d = dgrp * 256 + threadIdx.x;
    const int ch = b * DD + d;

    size_t base = ((size_t)(b * LL + chunk * TCHUNK)) * DD + d;
    float h = g_Carry[chunk * NCHAN + ch];
#pragma unroll 8
    for (int t = 0; t < TCHUNK; t++) {
        float g = g_G[base];
        float c = g_C[base];
        float bt = (1.0f - g) * c;
        h = fmaf(g, h, bt);
        out[base] = h;
        base += DD;
    }
}

// ---------------------------------------------------------------------------
extern "C" void kernel_launch(void* const* d_in, const int* in_sizes, int n_in,
                              void* d_out, int out_size)
{
    const float* x      = (const float*)d_in[0];
    const float* hidden = (const float*)d_in[1];
    const float* Wg     = (const float*)d_in[2];
    const float* bg     = (const float*)d_in[3];
    const float* Wh     = (const float*)d_in[4];
    const float* bh     = (const float*)d_in[5];
    float* out = (float*)d_out;

    static bool attr_set = false;
    if (!attr_set) {
        cudaFuncSetAttribute(gemm_mma_kernel,
                             cudaFuncAttributeMaxDynamicSharedMemorySize, SMEM_NEEDED);
        attr_set = true;
    }

    float *xr, *wr;
    cudaGetSymbolAddress((void**)&xr, g_Xr);
    cudaGetSymbolAddress((void**)&wr, g_Wr);

    // pre-round to tf32 (RNA): x -> g_Xr, [Wg;Wh] -> g_Wr
    {
        int n4 = MTOT * DD / 4;
        round_tf32_kernel<<<(n4 + 255) / 256, 256>>>(x, xr, n4);
        int w4 = DD * DD / 4;
        round_tf32_kernel<<<(w4 + 255) / 256, 256>>>(Wg, wr, w4);
        round_tf32_kernel<<<(w4 + 255) / 256, 256>>>(Wh, wr + (size_t)DD * DD, w4);
    }

    dim3 ggrid(NVIRT / BN, MTOT / BM);   // (16, 256)
    gemm_mma_kernel<<<ggrid, 256, SMEM_NEEDED>>>(bg, bh);

    scan_aggregate_kernel<<<BB * NCHUNK * (DD / 256), 256>>>();
    scan_carry_kernel<<<NCHAN / 256, 256>>>(hidden);
    scan_apply_kernel<<<BB * NCHUNK * (DD / 256), 256>>>(out);
}

// round 13
// speedup vs baseline: 1.5737x; 1.5737x over previous
#include <cuda_runtime.h>
#include <cstdint>
#include <math.h>

// ---------------- problem dims ----------------
#define BB 8
#define LL 4096
#define DD 1024
#define MTOT (BB * LL)            // 32768
#define NVIRT (2 * DD)            // 2048 virtual N (Wg | Wh)

// GEMM tiling (R8 proven config — do not restructure the mainloop:
// load-first + wait_group 2 + two syncs measured 644us; the single-barrier
// variant measured ~1005us (R10 regression)).
#define BM 128
#define BN 128
#define BK 32
#define NCH (DD / BK)             // 32 k-chunks
#define NS 3                      // pipeline stages

#define STAGE_A_BYTES (BM * BK * 4)   // 16 KB
#define STAGE_B_BYTES (BN * BK * 4)   // 16 KB
#define STAGE_BYTES (STAGE_A_BYTES + STAGE_B_BYTES)
#define SMEM_NEEDED (NS * STAGE_BYTES)   // 96 KB -> 2 CTA/SM

// scan chunking
#define NCHUNK 16
#define TCHUNK (LL / NCHUNK)      // 256
#define NCHAN (BB * DD)           // 8192

// ---------------- device scratch ----------------
// NOTE: g must be fp32 — the recurrence amplifies gate error by 1/(1-g);
// fp16 storage failed with rel_err 4.4e-2 (R9).
__device__ float g_G[(size_t)MTOT * DD];     // sigmoid gate
__device__ float g_C[(size_t)MTOT * DD];     // tanh candidate
__device__ float g_Wr[(size_t)NVIRT * DD];   // [Wg ; Wh] pre-rounded to tf32
__device__ float g_AggA[NCHUNK * NCHAN];
__device__ float g_AggB[NCHUNK * NCHAN];
__device__ float g_Carry[NCHUNK * NCHAN];

// ---------------- helpers ----------------
__device__ __forceinline__ uint32_t smem_to_u32(const void* p) {
    uint32_t a;
    asm("{ .reg .u64 t; cvta.to.shared.u64 t, %1; cvt.u32.u64 %0, t; }" : "=r"(a) : "l"(p));
    return a;
}
__device__ __forceinline__ void cp_async16(uint32_t saddr, const void* gaddr) {
    asm volatile("cp.async.cg.shared.global [%0], [%1], 16;" :: "r"(saddr), "l"(gaddr));
}
__device__ __forceinline__ void cp_commit() { asm volatile("cp.async.commit_group;" ::: "memory"); }
__device__ __forceinline__ void cp_wait2() { asm volatile("cp.async.wait_group 2;" ::: "memory"); }

__device__ __forceinline__ void ldsm_x4(uint32_t& r0, uint32_t& r1, uint32_t& r2, uint32_t& r3,
                                        uint32_t addr) {
    asm volatile("ldmatrix.sync.aligned.m8n8.x4.shared.b16 {%0,%1,%2,%3}, [%4];"
                 : "=r"(r0), "=r"(r1), "=r"(r2), "=r"(r3) : "r"(addr));
}
__device__ __forceinline__ void mma_tf32(float* c, const uint32_t* a, const uint32_t* b) {
    asm volatile(
        "mma.sync.aligned.m16n8k8.row.col.f32.tf32.tf32.f32 "
        "{%0,%1,%2,%3}, {%4,%5,%6,%7}, {%8,%9}, {%0,%1,%2,%3};"
        : "+f"(c[0]), "+f"(c[1]), "+f"(c[2]), "+f"(c[3])
        : "r"(a[0]), "r"(a[1]), "r"(a[2]), "r"(a[3]), "r"(b[0]), "r"(b[1]));
}
__device__ __forceinline__ float tanh_approx(float x) {
    float o;
    asm("tanh.approx.f32 %0, %1;" : "=f"(o) : "f"(x));
    return o;
}

// swizzled smem offset for (row, 16B-chunk) with 128B rows
__device__ __forceinline__ uint32_t sw_off(int row, int chunk) {
    return (uint32_t)(row * 128 + ((chunk ^ (row & 7)) << 4));
}

// ---------------------------------------------------------------------------
// tf32 pre-round (RNA) pass — W only (x is fed raw; HW truncates A operand).
// ---------------------------------------------------------------------------
__global__ __launch_bounds__(256)
void round_tf32_kernel(const float* __restrict__ in, float* __restrict__ out, int n4)
{
    int i = blockIdx.x * 256 + threadIdx.x;
    if (i >= n4) return;
    float4 v = ((const float4*)in)[i];
    uint32_t a, b, c, d;
    asm("cvt.rna.tf32.f32 %0, %1;" : "=r"(a) : "f"(v.x));
    asm("cvt.rna.tf32.f32 %0, %1;" : "=r"(b) : "f"(v.y));
    asm("cvt.rna.tf32.f32 %0, %1;" : "=r"(c) : "f"(v.z));
    asm("cvt.rna.tf32.f32 %0, %1;" : "=r"(d) : "f"(v.w));
    float4 o;
    o.x = __uint_as_float(a); o.y = __uint_as_float(b);
    o.z = __uint_as_float(c); o.w = __uint_as_float(d);
    ((float4*)out)[i] = o;
}

// ---------------------------------------------------------------------------
// tf32 mma.sync GEMM + bias + activation epilogue.
// grid = (NVIRT/BN = 16, MTOT/BM = 256), 256 threads (wm2 x wn4),
// warp tile 64x32. R8 multistage order: load -> commit -> wait2 -> sync ->
// compute -> sync.
// ---------------------------------------------------------------------------
__global__ __launch_bounds__(256, 2)
void gemm_mma_kernel(const float* __restrict__ x,
                     const float* __restrict__ bg, const float* __restrict__ bh)
{
    extern __shared__ char smem_raw[];
    const uint32_t s0 = smem_to_u32(smem_raw);

    const int tid = threadIdx.x;
    const int wid = tid >> 5;
    const int lane = tid & 31;
    const int wm = wid >> 2;          // 0..1  -> 64-row band
    const int wn = wid & 3;           // 0..3  -> 32-col band

    const int m0 = blockIdx.y * BM;
    const int n0 = blockIdx.x * BN;   // virtual col
    const bool second = (n0 >= DD);
    const int n0r = n0 & (DD - 1);
    const float* __restrict__ bias = second ? bh : bg;
    float* __restrict__ outp = second ? g_C : g_G;

    const float* xa0 = x + (size_t)m0 * DD;
    const float* wb0 = g_Wr + (size_t)n0 * DD;   // virtual row in [Wg;Wh]

    auto load_stage = [&](int s, int kc) {
        const uint32_t sa = s0 + (uint32_t)s * STAGE_BYTES;
        const uint32_t sb = sa + STAGE_A_BYTES;
        const int kt = kc * BK;
#pragma unroll
        for (int i = 0; i < 4; i++) {
            int u = i * 256 + tid;
            int r = u >> 3, c = u & 7;
            cp_async16(sa + sw_off(r, c), xa0 + (size_t)r * DD + kt + c * 4);
        }
#pragma unroll
        for (int i = 0; i < 4; i++) {
            int u = i * 256 + tid;
            int r = u >> 3, c = u & 7;
            cp_async16(sb + sw_off(r, c), wb0 + (size_t)r * DD + kt + c * 4);
        }
    };

    float acc[4][4][4];               // [m-tile][n-tile][frag]
#pragma unroll
    for (int i = 0; i < 4; i++)
#pragma unroll
        for (int j = 0; j < 4; j++)
#pragma unroll
            for (int q = 0; q < 4; q++) acc[i][j][q] = 0.f;

    // prologue: stages 0..NS-2
    load_stage(0, 0); cp_commit();
    load_stage(1, 1); cp_commit();

    const int q = lane >> 3, rr = lane & 7;

    for (int k = 0; k < NCH; k++) {
        const int kl = k + NS - 1;
        if (kl < NCH) load_stage(kl % NS, kl);
        cp_commit();
        cp_wait2();
        __syncthreads();

        const uint32_t sa = s0 + (uint32_t)(k % NS) * STAGE_BYTES;
        const uint32_t sb = sa + STAGE_A_BYTES;

#pragma unroll
        for (int kk8 = 0; kk8 < 4; kk8++) {      // four k8 steps in BK=32
            const int ch = kk8 * 2;              // 16B-chunk base (k8 = 2 chunks)
            uint32_t afr[4][4];
#pragma unroll
            for (int mt = 0; mt < 4; mt++) {
                int row = wm * 64 + mt * 16 + ((q & 1) << 3) + rr;
                int chunk = ch + (q >> 1);
                ldsm_x4(afr[mt][0], afr[mt][1], afr[mt][2], afr[mt][3],
                        sa + sw_off(row, chunk));
            }
            uint32_t bfr[4][2];
#pragma unroll
            for (int p = 0; p < 2; p++) {        // each x4 covers two n8-tiles
                int row = wn * 32 + p * 16 + ((q >> 1) << 3) + rr;
                int chunk = ch + (q & 1);
                uint32_t r0, r1, r2, r3;
                ldsm_x4(r0, r1, r2, r3, sb + sw_off(row, chunk));
                bfr[p * 2 + 0][0] = r0; bfr[p * 2 + 0][1] = r1;
                bfr[p * 2 + 1][0] = r2; bfr[p * 2 + 1][1] = r3;
            }
#pragma unroll
            for (int mt = 0; mt < 4; mt++)
#pragma unroll
                for (int nt = 0; nt < 4; nt++)
                    mma_tf32(acc[mt][nt], afr[mt], bfr[nt]);
        }
        __syncthreads();
    }

    // ---- epilogue: bias + activation, float2 stores ----
    const int crow = lane >> 2;            // 0..7
    const int ccol = (lane & 3) * 2;       // 0,2,4,6
#pragma unroll
    for (int nt = 0; nt < 4; nt++) {
        const int col = wn * 32 + nt * 8 + ccol;
        const float2 bv = *(const float2*)&bias[n0r + col];
#pragma unroll
        for (int mt = 0; mt < 4; mt++) {
#pragma unroll
            for (int h = 0; h < 2; h++) {  // c0/c1 then c2/c3 (row, row+8)
                const int m = m0 + wm * 64 + mt * 16 + crow + h * 8;
                float t0 = acc[mt][nt][h * 2 + 0] + bv.x;
                float t1 = acc[mt][nt][h * 2 + 1] + bv.y;
                float2 o;
                if (second) { o.x = tanh_approx(t0); o.y = tanh_approx(t1); }
                else {
                    o.x = 1.0f / (1.0f + __expf(-t0));
                    o.y = 1.0f / (1.0f + __expf(-t1));
                }
                *(float2*)&outp[(size_t)m * DD + n0r + col] = o;
            }
        }
    }
}

// ---------------------------------------------------------------------------
// Scan phase A: per (channel, chunk) affine aggregate over TCHUNK steps.
// ---------------------------------------------------------------------------
__global__ __launch_bounds__(256)
void scan_aggregate_kernel()
{
    const int bx = blockIdx.x;
    const int dgrp = bx & 3;
    const int chunk = (bx >> 2) & (NCHUNK - 1);
    const int b = bx >> 6;
    const int d = dgrp * 256 + threadIdx.x;

    size_t base = ((size_t)(b * LL + chunk * TCHUNK)) * DD + d;
    float A = 1.0f, Bc = 0.0f;
#pragma unroll 8
    for (int t = 0; t < TCHUNK; t++) {
        float g = g_G[base];
        float c = g_C[base];
        float bt = (1.0f - g) * c;
        Bc = fmaf(g, Bc, bt);
        A *= g;
        base += DD;
    }
    const int ch = b * DD + d;
    g_AggA[chunk * NCHAN + ch] = A;
    g_AggB[chunk * NCHAN + ch] = Bc;
}

// ---------------------------------------------------------------------------
// Scan phase B: sequential scan of chunk aggregates per channel.
// ---------------------------------------------------------------------------
__global__ __launch_bounds__(256)
void scan_carry_kernel(const float* __restrict__ hidden)
{
    const int ch = blockIdx.x * 256 + threadIdx.x;
    float h = hidden[ch];
#pragma unroll
    for (int k = 0; k < NCHUNK; k++) {
        g_Carry[k * NCHAN + ch] = h;
        h = fmaf(g_AggA[k * NCHAN + ch], h, g_AggB[k * NCHAN + ch]);
    }
}

// ---------------------------------------------------------------------------
// Scan phase C: apply within-chunk recurrence from carry, write output.
// ---------------------------------------------------------------------------
__global__ __launch_bounds__(256)
void scan_apply_kernel(float* __restrict__ out)
{
    const int bx = blockIdx.x;
    const int dgrp = bx & 3;
    const int chunk = (bx >> 2) & (NCHUNK - 1);
    const int b = bx >> 6;
    const int d = dgrp * 256 + threadIdx.x;
    const int ch = b * DD + d;

    size_t base = ((size_t)(b * LL + chunk * TCHUNK)) * DD + d;
    float h = g_Carry[chunk * NCHAN + ch];
#pragma unroll 8
    for (int t = 0; t < TCHUNK; t++) {
        float g = g_G[base];
        float c = g_C[base];
        float bt = (1.0f - g) * c;
        h = fmaf(g, h, bt);
        out[base] = h;
        base += DD;
    }
}

// ---------------------------------------------------------------------------
extern "C" void kernel_launch(void* const* d_in, const int* in_sizes, int n_in,
                              void* d_out, int out_size)
{
    const float* x      = (const float*)d_in[0];
    const float* hidden = (const float*)d_in[1];
    const float* Wg     = (const float*)d_in[2];
    const float* bg     = (const float*)d_in[3];
    const float* Wh     = (const float*)d_in[4];
    const float* bh     = (const float*)d_in[5];
    float* out = (float*)d_out;

    static bool attr_set = false;
    if (!attr_set) {
        cudaFuncSetAttribute(gemm_mma_kernel,
                             cudaFuncAttributeMaxDynamicSharedMemorySize, SMEM_NEEDED);
        attr_set = true;
    }

    float* wr;
    cudaGetSymbolAddress((void**)&wr, g_Wr);

    // pre-round W to tf32 (RNA): [Wg;Wh] -> g_Wr  (x fed raw; HW truncates)
    {
        int w4 = DD * DD / 4;
        round_tf32_kernel<<<(w4 + 255) / 256, 256>>>(Wg, wr, w4);
        round_tf32_kernel<<<(w4 + 255) / 256, 256>>>(Wh, wr + (size_t)DD * DD, w4);
    }

    dim3 ggrid(NVIRT / BN, MTOT / BM);   // (16, 256)
    gemm_mma_kernel<<<ggrid, 256, SMEM_NEEDED>>>(x, bg, bh);

    scan_aggregate_kernel<<<BB * NCHUNK * (DD / 256), 256>>>();
    scan_carry_kernel<<<NCHAN / 256, 256>>>(hidden);
    scan_apply_kernel<<<BB * NCHUNK * (DD / 256), 256>>>(out);
}

// round 15
// speedup vs baseline: 1.5828x; 1.0058x over previous
#include <cuda_runtime.h>
#include <cuda_fp16.h>
#include <cstdint>
#include <math.h>

// ---------------- problem dims ----------------
#define BB 8
#define LL 4096
#define DD 1024
#define MTOT (BB * LL)            // 32768
#define NVIRT (2 * DD)            // 2048 virtual N (Wg | Wh)

// GEMM tiling (R8 proven config — do not restructure the mainloop:
// load-first + wait_group 2 + two syncs measured 644us; the single-barrier
// variant measured ~1005us (R10 regression)).
#define BM 128
#define BN 128
#define BK 32
#define NCH (DD / BK)             // 32 k-chunks
#define NS 3                      // pipeline stages

#define STAGE_A_BYTES (BM * BK * 4)   // 16 KB
#define STAGE_B_BYTES (BN * BK * 4)   // 16 KB
#define STAGE_BYTES (STAGE_A_BYTES + STAGE_B_BYTES)
#define SMEM_NEEDED (NS * STAGE_BYTES)   // 96 KB -> 2 CTA/SM

// scan chunking
#define NCHUNK 16
#define TCHUNK (LL / NCHUNK)      // 256
#define NCHAN (BB * DD)           // 8192

// ---------------- device scratch ----------------
// NOTE: g MUST stay fp32 — the recurrence amplifies gate error by 1/(1-g);
// fp16 g failed with rel_err 4.4e-2 (R9). c is safe in fp16: its error is
// NOT amplified (per-step weight (1-g), geometric sum = 1).
__device__ float  g_G[(size_t)MTOT * DD];     // sigmoid gate (fp32)
__device__ __half g_Ch[(size_t)MTOT * DD];    // tanh candidate (fp16)
__device__ float  g_Wr[(size_t)NVIRT * DD];   // [Wg ; Wh] pre-rounded to tf32
__device__ float  g_AggA[NCHUNK * NCHAN];
__device__ float  g_AggB[NCHUNK * NCHAN];
__device__ float  g_Carry[NCHUNK * NCHAN];

// ---------------- helpers ----------------
__device__ __forceinline__ uint32_t smem_to_u32(const void* p) {
    uint32_t a;
    asm("{ .reg .u64 t; cvta.to.shared.u64 t, %1; cvt.u32.u64 %0, t; }" : "=r"(a) : "l"(p));
    return a;
}
__device__ __forceinline__ void cp_async16(uint32_t saddr, const void* gaddr) {
    asm volatile("cp.async.cg.shared.global [%0], [%1], 16;" :: "r"(saddr), "l"(gaddr));
}
__device__ __forceinline__ void cp_commit() { asm volatile("cp.async.commit_group;" ::: "memory"); }
__device__ __forceinline__ void cp_wait2() { asm volatile("cp.async.wait_group 2;" ::: "memory"); }

__device__ __forceinline__ void ldsm_x4(uint32_t& r0, uint32_t& r1, uint32_t& r2, uint32_t& r3,
                                        uint32_t addr) {
    asm volatile("ldmatrix.sync.aligned.m8n8.x4.shared.b16 {%0,%1,%2,%3}, [%4];"
                 : "=r"(r0), "=r"(r1), "=r"(r2), "=r"(r3) : "r"(addr));
}
__device__ __forceinline__ void mma_tf32(float* c, const uint32_t* a, const uint32_t* b) {
    asm volatile(
        "mma.sync.aligned.m16n8k8.row.col.f32.tf32.tf32.f32 "
        "{%0,%1,%2,%3}, {%4,%5,%6,%7}, {%8,%9}, {%0,%1,%2,%3};"
        : "+f"(c[0]), "+f"(c[1]), "+f"(c[2]), "+f"(c[3])
        : "r"(a[0]), "r"(a[1]), "r"(a[2]), "r"(a[3]), "r"(b[0]), "r"(b[1]));
}
__device__ __forceinline__ float tanh_approx(float x) {
    float o;
    asm("tanh.approx.f32 %0, %1;" : "=f"(o) : "f"(x));
    return o;
}

// swizzled smem offset for (row, 16B-chunk) with 128B rows
__device__ __forceinline__ uint32_t sw_off(int row, int chunk) {
    return (uint32_t)(row * 128 + ((chunk ^ (row & 7)) << 4));
}

// ---------------------------------------------------------------------------
// tf32 pre-round (RNA) pass — W only (x is fed raw; HW truncates A operand).
// ---------------------------------------------------------------------------
__global__ __launch_bounds__(256)
void round_tf32_kernel(const float* __restrict__ in, float* __restrict__ out, int n4)
{
    int i = blockIdx.x * 256 + threadIdx.x;
    if (i >= n4) return;
    float4 v = ((const float4*)in)[i];
    uint32_t a, b, c, d;
    asm("cvt.rna.tf32.f32 %0, %1;" : "=r"(a) : "f"(v.x));
    asm("cvt.rna.tf32.f32 %0, %1;" : "=r"(b) : "f"(v.y));
    asm("cvt.rna.tf32.f32 %0, %1;" : "=r"(c) : "f"(v.z));
    asm("cvt.rna.tf32.f32 %0, %1;" : "=r"(d) : "f"(v.w));
    float4 o;
    o.x = __uint_as_float(a); o.y = __uint_as_float(b);
    o.z = __uint_as_float(c); o.w = __uint_as_float(d);
    ((float4*)out)[i] = o;
}

// ---------------------------------------------------------------------------
// tf32 mma.sync GEMM + bias + activation epilogue.
// grid = (NVIRT/BN = 16, MTOT/BM = 256), 256 threads (wm2 x wn4),
// warp tile 64x32. R8 multistage order: load -> commit -> wait2 -> sync ->
// compute -> sync.
// ---------------------------------------------------------------------------
__global__ __launch_bounds__(256, 2)
void gemm_mma_kernel(const float* __restrict__ x,
                     const float* __restrict__ bg, const float* __restrict__ bh)
{
    extern __shared__ char smem_raw[];
    const uint32_t s0 = smem_to_u32(smem_raw);

    const int tid = threadIdx.x;
    const int wid = tid >> 5;
    const int lane = tid & 31;
    const int wm = wid >> 2;          // 0..1  -> 64-row band
    const int wn = wid & 3;           // 0..3  -> 32-col band

    const int m0 = blockIdx.y * BM;
    const int n0 = blockIdx.x * BN;   // virtual col
    const bool second = (n0 >= DD);
    const int n0r = n0 & (DD - 1);
    const float* __restrict__ bias = second ? bh : bg;

    const float* xa0 = x + (size_t)m0 * DD;
    const float* wb0 = g_Wr + (size_t)n0 * DD;   // virtual row in [Wg;Wh]

    auto load_stage = [&](int s, int kc) {
        const uint32_t sa = s0 + (uint32_t)s * STAGE_BYTES;
        const uint32_t sb = sa + STAGE_A_BYTES;
        const int kt = kc * BK;
#pragma unroll
        for (int i = 0; i < 4; i++) {
            int u = i * 256 + tid;
            int r = u >> 3, c = u & 7;
            cp_async16(sa + sw_off(r, c), xa0 + (size_t)r * DD + kt + c * 4);
        }
#pragma unroll
        for (int i = 0; i < 4; i++) {
            int u = i * 256 + tid;
            int r = u >> 3, c = u & 7;
            cp_async16(sb + sw_off(r, c), wb0 + (size_t)r * DD + kt + c * 4);
        }
    };

    float acc[4][4][4];               // [m-tile][n-tile][frag]
#pragma unroll
    for (int i = 0; i < 4; i++)
#pragma unroll
        for (int j = 0; j < 4; j++)
#pragma unroll
            for (int q = 0; q < 4; q++) acc[i][j][q] = 0.f;

    // prologue: stages 0..NS-2
    load_stage(0, 0); cp_commit();
    load_stage(1, 1); cp_commit();

    const int q = lane >> 3, rr = lane & 7;

    for (int k = 0; k < NCH; k++) {
        const int kl = k + NS - 1;
        if (kl < NCH) load_stage(kl % NS, kl);
        cp_commit();
        cp_wait2();
        __syncthreads();

        const uint32_t sa = s0 + (uint32_t)(k % NS) * STAGE_BYTES;
        const uint32_t sb = sa + STAGE_A_BYTES;

#pragma unroll
        for (int kk8 = 0; kk8 < 4; kk8++) {      // four k8 steps in BK=32
            const int ch = kk8 * 2;              // 16B-chunk base (k8 = 2 chunks)
            uint32_t afr[4][4];
#pragma unroll
            for (int mt = 0; mt < 4; mt++) {
                int row = wm * 64 + mt * 16 + ((q & 1) << 3) + rr;
                int chunk = ch + (q >> 1);
                ldsm_x4(afr[mt][0], afr[mt][1], afr[mt][2], afr[mt][3],
                        sa + sw_off(row, chunk));
            }
            uint32_t bfr[4][2];
#pragma unroll
            for (int p = 0; p < 2; p++) {        // each x4 covers two n8-tiles
                int row = wn * 32 + p * 16 + ((q >> 1) << 3) + rr;
                int chunk = ch + (q & 1);
                uint32_t r0, r1, r2, r3;
                ldsm_x4(r0, r1, r2, r3, sb + sw_off(row, chunk));
                bfr[p * 2 + 0][0] = r0; bfr[p * 2 + 0][1] = r1;
                bfr[p * 2 + 1][0] = r2; bfr[p * 2 + 1][1] = r3;
            }
#pragma unroll
            for (int mt = 0; mt < 4; mt++)
#pragma unroll
                for (int nt = 0; nt < 4; nt++)
                    mma_tf32(acc[mt][nt], afr[mt], bfr[nt]);
        }
        __syncthreads();
    }

    // ---- epilogue: bias + activation ----
    // first half (sigmoid) -> g_G fp32 float2 stores
    // second half (tanh)   -> g_Ch fp16 half2 stores
    const int crow = lane >> 2;            // 0..7
    const int ccol = (lane & 3) * 2;       // 0,2,4,6 (even)
#pragma unroll
    for (int nt = 0; nt < 4; nt++) {
        const int col = wn * 32 + nt * 8 + ccol;
        const float2 bv = *(const float2*)&bias[n0r + col];
#pragma unroll
        for (int mt = 0; mt < 4; mt++) {
#pragma unroll
            for (int h = 0; h < 2; h++) {  // c0/c1 then c2/c3 (row, row+8)
                const int m = m0 + wm * 64 + mt * 16 + crow + h * 8;
                float t0 = acc[mt][nt][h * 2 + 0] + bv.x;
                float t1 = acc[mt][nt][h * 2 + 1] + bv.y;
                if (second) {
                    *(__half2*)&g_Ch[(size_t)m * DD + n0r + col] =
                        __floats2half2_rn(tanh_approx(t0), tanh_approx(t1));
                } else {
                    float2 o;
                    o.x = __fdividef(1.0f, 1.0f + __expf(-t0));
                    o.y = __fdividef(1.0f, 1.0f + __expf(-t1));
                    *(float2*)&g_G[(size_t)m * DD + n0r + col] = o;
                }
            }
        }
    }
}

// ---------------------------------------------------------------------------
// Scan phase A: per (channel, chunk) affine aggregate over TCHUNK steps.
// ---------------------------------------------------------------------------
__global__ __launch_bounds__(256)
void scan_aggregate_kernel()
{
    const int bx = blockIdx.x;
    const int dgrp = bx & 3;
    const int chunk = (bx >> 2) & (NCHUNK - 1);
    const int b = bx >> 6;
    const int d = dgrp * 256 + threadIdx.x;

    size_t base = ((size_t)(b * LL + chunk * TCHUNK)) * DD + d;
    float A = 1.0f, Bc = 0.0f;
#pragma unroll 8
    for (int t = 0; t < TCHUNK; t++) {
        float g = g_G[base];
        float c = __half2float(g_Ch[base]);
        float bt = (1.0f - g) * c;
        Bc = fmaf(g, Bc, bt);
        A *= g;
        base += DD;
    }
    const int ch = b * DD + d;
    g_AggA[chunk * NCHAN + ch] = A;
    g_AggB[chunk * NCHAN + ch] = Bc;
}

// ---------------------------------------------------------------------------
// Scan phase B: sequential scan of chunk aggregates per channel.
// ---------------------------------------------------------------------------
__global__ __launch_bounds__(256)
void scan_carry_kernel(const float* __restrict__ hidden)
{
    const int ch = blockIdx.x * 256 + threadIdx.x;
    float h = hidden[ch];
#pragma unroll
    for (int k = 0; k < NCHUNK; k++) {
        g_Carry[k * NCHAN + ch] = h;
        h = fmaf(g_AggA[k * NCHAN + ch], h, g_AggB[k * NCHAN + ch]);
    }
}

// ---------------------------------------------------------------------------
// Scan phase C: apply within-chunk recurrence from carry, write output.
// ---------------------------------------------------------------------------
__global__ __launch_bounds__(256)
void scan_apply_kernel(float* __restrict__ out)
{
    const int bx = blockIdx.x;
    const int dgrp = bx & 3;
    const int chunk = (bx >> 2) & (NCHUNK - 1);
    const int b = bx >> 6;
    const int d = dgrp * 256 + threadIdx.x;
    const int ch = b * DD + d;

    size_t base = ((size_t)(b * LL + chunk * TCHUNK)) * DD + d;
    float h = g_Carry[chunk * NCHAN + ch];
#pragma unroll 8
    for (int t = 0; t < TCHUNK; t++) {
        float g = g_G[base];
        float c = __half2float(g_Ch[base]);
        float bt = (1.0f - g) * c;
        h = fmaf(g, h, bt);
        out[base] = h;
        base += DD;
    }
}

// ---------------------------------------------------------------------------
extern "C" void kernel_launch(void* const* d_in, const int* in_sizes, int n_in,
                              void* d_out, int out_size)
{
    const float* x      = (const float*)d_in[0];
    const float* hidden = (const float*)d_in[1];
    const float* Wg     = (const float*)d_in[2];
    const float* bg     = (const float*)d_in[3];
    const float* Wh     = (const float*)d_in[4];
    const float* bh     = (const float*)d_in[5];
    float* out = (float*)d_out;

    static bool attr_set = false;
    if (!attr_set) {
        cudaFuncSetAttribute(gemm_mma_kernel,
                             cudaFuncAttributeMaxDynamicSharedMemorySize, SMEM_NEEDED);
        attr_set = true;
    }

    float* wr;
    cudaGetSymbolAddress((void**)&wr, g_Wr);

    // pre-round W to tf32 (RNA): [Wg;Wh] -> g_Wr  (x fed raw; HW truncates)
    {
        int w4 = DD * DD / 4;
        round_tf32_kernel<<<(w4 + 255) / 256, 256>>>(Wg, wr, w4);
        round_tf32_kernel<<<(w4 + 255) / 256, 256>>>(Wh, wr + (size_t)DD * DD, w4);
    }

    dim3 ggrid(NVIRT / BN, MTOT / BM);   // (16, 256)
    gemm_mma_kernel<<<ggrid, 256, SMEM_NEEDED>>>(x, bg, bh);

    scan_aggregate_kernel<<<BB * NCHUNK * (DD / 256), 256>>>();
    scan_carry_kernel<<<NCHAN / 256, 256>>>(hidden);
    scan_apply_kernel<<<BB * NCHUNK * (DD / 256), 256>>>(out);
}